// round 5
// baseline (speedup 1.0000x reference)
#include <cuda_runtime.h>
#include <cuda_bf16.h>
#include <math.h>
#include <stdint.h>

// Problem constants
#define B_   64
#define L_   500
#define F_   256
#define H_   4
#define DK_  64
#define BH_  (B_ * H_)      // 256
#define ROWS_ (B_ * L_)     // 32000

// -------- scratch (device globals; no allocations allowed) ---------
__device__ float g_Wc[F_ * F_];                         // combined q-proj weight (per-head w_qs_h @ w1)
__device__ float g_weight[(size_t)BH_ * L_ * DK_];      // relu(q Wc + b1), [b][h][l][d]
__device__ float g_vh[(size_t)BH_ * L_ * DK_];          // v w_vs,           [b][h][l][d]
__device__ float g_attnout[(size_t)ROWS_ * F_];         // attention output  [b*l][f]
__device__ float g_x[(size_t)ROWS_ * F_];               // fc + residual (pre-LN)

// ===================================================================
// Kernel 0: Wc[k][h*64+j] = sum_d w_qs[k][h*64+d] * w1[d][j]
// ===================================================================
__global__ void wc_kernel(const float* __restrict__ w_qs,
                          const float* __restrict__ w1) {
    int k = blockIdx.x;          // 0..255
    int n = threadIdx.x;         // 0..255
    int h = n >> 6, j = n & 63;
    const float* wq = w_qs + k * F_ + h * DK_;
    float acc = 0.f;
    #pragma unroll 8
    for (int d = 0; d < DK_; d++)
        acc += wq[d] * w1[d * DK_ + j];
    g_Wc[k * F_ + n] = acc;
}

// ===================================================================
// Kernel 1/2/4: tiled GEMM  C(64x64 tile) = A[rows,256] * Bw[256,256]
// grid: (nt=4, mt=8, b=64), block 256 (16x16 logical)
// MODE 0: out -> head layout [b][h=nt][l][d], no epilogue   (v proj)
// MODE 1: out -> head layout, +bias[d], relu                (q proj)
// MODE 2: out -> flat [b*l][f], + residual ep[b*l][f]       (fc)
// ===================================================================
template <int MODE>
__global__ void gemm_kernel(const float* __restrict__ A,
                            const float* __restrict__ Bw,
                            const float* __restrict__ ep,   // bias (MODE1) or residual (MODE2)
                            float* __restrict__ Cout) {
    __shared__ float sA[64 * 20];   // [r][kk], stride 20 (pad)
    __shared__ float sB[16 * 68];   // [kk][c], stride 68 (pad)

    int nt = blockIdx.x, mt = blockIdx.y, b = blockIdx.z;
    int tid = threadIdx.x;
    int ty = tid >> 4, tx = tid & 15;
    int l0 = mt * 64;
    const float* Ab = A + (size_t)b * L_ * F_;

    float acc[4][4];
    #pragma unroll
    for (int i = 0; i < 4; i++)
        #pragma unroll
        for (int j = 0; j < 4; j++) acc[i][j] = 0.f;

    for (int k0 = 0; k0 < F_; k0 += 16) {
        // A tile 64x16 (one float4 per thread)
        {
            int r  = tid >> 2;
            int kv = (tid & 3) * 4;
            int l  = l0 + r;
            float4 v = make_float4(0.f, 0.f, 0.f, 0.f);
            if (l < L_) v = *(const float4*)(Ab + (size_t)l * F_ + k0 + kv);
            *(float4*)&sA[r * 20 + kv] = v;
        }
        // B tile 16x64 (one float4 per thread)
        {
            int kk = tid >> 4;
            int cv = (tid & 15) * 4;
            float4 v = *(const float4*)(Bw + (size_t)(k0 + kk) * F_ + nt * 64 + cv);
            *(float4*)&sB[kk * 68 + cv] = v;
        }
        __syncthreads();
        #pragma unroll
        for (int kk = 0; kk < 16; kk++) {
            float4 b4 = *(const float4*)&sB[kk * 68 + tx * 4];
            #pragma unroll
            for (int i = 0; i < 4; i++) {
                float a = sA[(ty * 4 + i) * 20 + kk];
                acc[i][0] += a * b4.x;
                acc[i][1] += a * b4.y;
                acc[i][2] += a * b4.z;
                acc[i][3] += a * b4.w;
            }
        }
        __syncthreads();
    }

    // epilogue + store
    #pragma unroll
    for (int i = 0; i < 4; i++) {
        int l = l0 + ty * 4 + i;
        if (l >= L_) continue;
        int c0 = tx * 4;
        float v0 = acc[i][0], v1 = acc[i][1], v2 = acc[i][2], v3 = acc[i][3];
        if (MODE == 1) {
            v0 = fmaxf(v0 + ep[c0 + 0], 0.f);
            v1 = fmaxf(v1 + ep[c0 + 1], 0.f);
            v2 = fmaxf(v2 + ep[c0 + 2], 0.f);
            v3 = fmaxf(v3 + ep[c0 + 3], 0.f);
        }
        if (MODE == 2) {
            const float4 rv = *(const float4*)(ep + ((size_t)b * L_ + l) * F_ + nt * 64 + c0);
            v0 += rv.x; v1 += rv.y; v2 += rv.z; v3 += rv.w;
        }
        float4 o = make_float4(v0, v1, v2, v3);
        if (MODE == 2) {
            *(float4*)(Cout + ((size_t)b * L_ + l) * F_ + nt * 64 + c0) = o;
        } else {
            *(float4*)(Cout + (((size_t)b * H_ + nt) * L_ + l) * (size_t)DK_ + c0) = o;
        }
    }
}

// ===================================================================
// Kernel 3: fused dense-synthesizer attention (flash-style online softmax)
//   S = weight_tile[64 rows, 64] @ w2[64, j-tile] + b2
//   P = softmax-online(S);  O += P @ vh[j-tile, 64]
// grid: (bh=256, mt=8), block 256, dynamic smem
// ===================================================================
#define ASTR 68
__global__ void attn_kernel(const float* __restrict__ w2,
                            const float* __restrict__ b2,
                            const float* __restrict__ weight,
                            const float* __restrict__ vh,
                            float* __restrict__ attnout) {
    extern __shared__ float sm[];
    float* sW  = sm;                   // [64][ASTR]  weight rows (r, d)
    float* sW2 = sW  + 64 * ASTR;      // [64][ASTR]  w2 (d, jj)
    float* sV  = sW2 + 64 * ASTR;      // [64][ASTR]  vh (jj, d)
    float* sP  = sV  + 64 * ASTR;      // [64][ASTR]  probabilities (r, jj)
    float* sB2 = sP  + 64 * ASTR;      // [64]

    int bh = blockIdx.x;
    int mt = blockIdx.y;
    int r0 = mt * 64;
    int tid = threadIdx.x;
    int ty = tid >> 4, tx = tid & 15;

    const float* wbase = weight + (size_t)bh * L_ * DK_;
    const float* vbase = vh + (size_t)bh * L_ * DK_;

    // load this block's 64 weight rows, FULL 64 cols (4 float4 per thread)
    #pragma unroll
    for (int it = 0; it < 4; it++) {
        int idx = tid + it * 256;       // 0..1023
        int r   = idx >> 4;             // 0..63
        int dv  = (idx & 15) * 4;       // 0..60
        int row = r0 + r;
        float4 v = make_float4(0.f, 0.f, 0.f, 0.f);
        if (row < L_) v = *(const float4*)(wbase + (size_t)row * DK_ + dv);
        *(float4*)&sW[r * ASTR + dv] = v;
    }

    float m_run[4], l_run[4], o[4][4];
    #pragma unroll
    for (int i = 0; i < 4; i++) {
        m_run[i] = -3.0e38f;
        l_run[i] = 0.f;
        #pragma unroll
        for (int j = 0; j < 4; j++) o[i][j] = 0.f;
    }

    for (int jt = 0; jt < 8; jt++) {
        int j0 = jt * 64;
        __syncthreads();   // protect smem reuse across iterations (also covers sW on jt=0)

        // load w2 tile [d][jj] : full 64x64 (16 scalars per thread; 500-row
        // stride makes clean float4 only sometimes — keep it scalar)
        #pragma unroll
        for (int it = 0; it < 16; it++) {
            int idx = tid + it * 256;   // 0..4095
            int d = idx >> 6;           // 0..63
            int jj = idx & 63;
            int j = j0 + jj;
            sW2[d * ASTR + jj] = (j < L_) ? w2[d * 500 + j] : 0.f;
        }
        // load vh tile [jj][d] : full 64x64 (4 float4 per thread)
        #pragma unroll
        for (int it = 0; it < 4; it++) {
            int idx = tid + it * 256;   // 0..1023
            int jj = idx >> 4;          // 0..63
            int dv = (idx & 15) * 4;    // 0..60
            int j = j0 + jj;
            float4 v = make_float4(0.f, 0.f, 0.f, 0.f);
            if (j < L_) v = *(const float4*)(vbase + (size_t)j * DK_ + dv);
            *(float4*)&sV[jj * ASTR + dv] = v;
        }
        // bias (= -1e30 beyond L -> exp underflows to 0, masks the column)
        if (tid < 64) {
            int j = j0 + tid;
            sB2[tid] = (j < L_) ? b2[j] : -1.0e30f;
        }
        __syncthreads();

        // S = sW @ sW2 + b2
        float s[4][4];
        #pragma unroll
        for (int i = 0; i < 4; i++)
            #pragma unroll
            for (int j = 0; j < 4; j++)
                s[i][j] = sB2[tx * 4 + j];
        #pragma unroll 4
        for (int kk = 0; kk < 64; kk++) {
            float4 b4 = *(const float4*)&sW2[kk * ASTR + tx * 4];
            #pragma unroll
            for (int i = 0; i < 4; i++) {
                float a = sW[(ty * 4 + i) * ASTR + kk];
                s[i][0] += a * b4.x;
                s[i][1] += a * b4.y;
                s[i][2] += a * b4.z;
                s[i][3] += a * b4.w;
            }
        }

        // online softmax update (row = ty*4+i; 16 lanes sharing ty hold the row)
        #pragma unroll
        for (int i = 0; i < 4; i++) {
            float m = fmaxf(fmaxf(s[i][0], s[i][1]), fmaxf(s[i][2], s[i][3]));
            #pragma unroll
            for (int off = 1; off < 16; off <<= 1)
                m = fmaxf(m, __shfl_xor_sync(0xffffffffu, m, off));
            float newm = fmaxf(m_run[i], m);
            float alpha = __expf(m_run[i] - newm);   // first tile: exp(-huge)=0
            float rs = 0.f;
            #pragma unroll
            for (int j = 0; j < 4; j++) {
                float p = __expf(s[i][j] - newm);
                s[i][j] = p;
                rs += p;
            }
            #pragma unroll
            for (int off = 1; off < 16; off <<= 1)
                rs += __shfl_xor_sync(0xffffffffu, rs, off);
            l_run[i] = l_run[i] * alpha + rs;
            m_run[i] = newm;
            o[i][0] *= alpha; o[i][1] *= alpha; o[i][2] *= alpha; o[i][3] *= alpha;
        }

        // stage P in smem
        #pragma unroll
        for (int i = 0; i < 4; i++)
            *(float4*)&sP[(ty * 4 + i) * ASTR + tx * 4] =
                make_float4(s[i][0], s[i][1], s[i][2], s[i][3]);
        __syncthreads();

        // O += P @ V
        #pragma unroll 4
        for (int jj = 0; jj < 64; jj++) {
            float4 v4 = *(const float4*)&sV[jj * ASTR + tx * 4];
            #pragma unroll
            for (int i = 0; i < 4; i++) {
                float p = sP[(ty * 4 + i) * ASTR + jj];
                o[i][0] += p * v4.x;
                o[i][1] += p * v4.y;
                o[i][2] += p * v4.z;
                o[i][3] += p * v4.w;
            }
        }
    }

    // normalize + store to [b][l][h*64+d]
    int b = bh >> 2, h = bh & 3;
    #pragma unroll
    for (int i = 0; i < 4; i++) {
        int row = r0 + ty * 4 + i;
        if (row >= L_) continue;
        float inv = 1.f / l_run[i];
        float4 ov = make_float4(o[i][0] * inv, o[i][1] * inv, o[i][2] * inv, o[i][3] * inv);
        *(float4*)(attnout + ((size_t)b * L_ + row) * F_ + h * DK_ + tx * 4) = ov;
    }
}

// ===================================================================
// Kernel 5: LayerNorm per row (256 cols), grid = 32000, block 256
// ===================================================================
__global__ void ln_kernel(const float* __restrict__ x,
                          const float* __restrict__ gam,
                          const float* __restrict__ bet,
                          float* __restrict__ out) {
    int row = blockIdx.x;
    int tid = threadIdx.x;
    float v = x[(size_t)row * F_ + tid];
    float s = v, s2 = v * v;
    #pragma unroll
    for (int off = 16; off; off >>= 1) {
        s  += __shfl_xor_sync(0xffffffffu, s,  off);
        s2 += __shfl_xor_sync(0xffffffffu, s2, off);
    }
    __shared__ float ws[8], ws2[8];
    int w = tid >> 5, lane = tid & 31;
    if (lane == 0) { ws[w] = s; ws2[w] = s2; }
    __syncthreads();
    float ts = 0.f, ts2 = 0.f;
    #pragma unroll
    for (int i = 0; i < 8; i++) { ts += ws[i]; ts2 += ws2[i]; }
    float mu  = ts * (1.f / F_);
    float var = ts2 * (1.f / F_) - mu * mu;
    float r = rsqrtf(var + 1e-6f);
    out[(size_t)row * F_ + tid] = (v - mu) * r * gam[tid] + bet[tid];
}

// ===================================================================
// launch
// ===================================================================
extern "C" void kernel_launch(void* const* d_in, const int* in_sizes, int n_in,
                              void* d_out, int out_size) {
    (void)in_sizes; (void)n_in; (void)out_size;
    const float* q    = (const float*)d_in[0];
    // d_in[1] = k : unused by the reference computation
    const float* v    = (const float*)d_in[2];
    const float* w_qs = (const float*)d_in[3];
    const float* w_vs = (const float*)d_in[4];
    const float* w1   = (const float*)d_in[5];
    const float* b1   = (const float*)d_in[6];
    const float* w2   = (const float*)d_in[7];
    const float* b2   = (const float*)d_in[8];
    const float* fc_w = (const float*)d_in[9];
    const float* ln_g = (const float*)d_in[10];
    const float* ln_b = (const float*)d_in[11];
    float* out = (float*)d_out;

    float *Wc_p, *weight_p, *vh_p, *attn_p, *x_p;
    cudaGetSymbolAddress((void**)&Wc_p,     g_Wc);
    cudaGetSymbolAddress((void**)&weight_p, g_weight);
    cudaGetSymbolAddress((void**)&vh_p,     g_vh);
    cudaGetSymbolAddress((void**)&attn_p,   g_attnout);
    cudaGetSymbolAddress((void**)&x_p,      g_x);

    const int attn_smem = 4 * 64 * ASTR * (int)sizeof(float) + 64 * (int)sizeof(float);
    cudaFuncSetAttribute(attn_kernel, cudaFuncAttributeMaxDynamicSharedMemorySize, attn_smem);

    // 0) combined q-projection weight
    wc_kernel<<<256, 256>>>(w_qs, w1);

    dim3 gg(4, 8, 64);
    // 1) weight = relu(q @ Wc + b1) -> [b][h][l][d]
    gemm_kernel<1><<<gg, 256>>>(q, Wc_p, b1, weight_p);
    // 2) vh = v @ w_vs -> [b][h][l][d]
    gemm_kernel<0><<<gg, 256>>>(v, w_vs, nullptr, vh_p);
    // 3) fused synthesizer attention
    attn_kernel<<<dim3(BH_, 8), 256, attn_smem>>>(w2, b2, weight_p, vh_p, attn_p);
    // 4) x = attnout @ fc_w + q
    gemm_kernel<2><<<gg, 256>>>(attn_p, fc_w, q, x_p);
    // 5) LayerNorm
    ln_kernel<<<ROWS_, 256>>>(x_p, ln_g, ln_b, out);
}